// round 1
// baseline (speedup 1.0000x reference)
#include <cuda_runtime.h>
#include <cuda_bf16.h>
#include <math.h>

// Problem constants (fixed-shape problem)
#define EMB 128
#define NHEAD 8
#define DHEAD 16
#define KNBR 32
#define NMAX 2048

// Scratch (no cudaMalloc allowed)
__device__ float g_cent[NMAX * 3];
__device__ float g_pos [NMAX * EMB];
__device__ float g_qkv [NMAX * 3 * EMB];
__device__ int   g_nbr [NMAX * KNBR];
__device__ float g_o   [NMAX * EMB];

// ---------------------------------------------------------------------------
// Stage 1: centroids, positional encoder (Linear->GELU->LayerNorm), pos_enhanced
// ---------------------------------------------------------------------------
__global__ __launch_bounds__(128) void prep_kernel(
    const float* __restrict__ x, const float* __restrict__ coords9,
    const float* __restrict__ prompt,
    const float* __restrict__ pe_w, const float* __restrict__ pe_b,
    const float* __restrict__ pe_g, const float* __restrict__ pe_bt, int n)
{
    int i = blockIdx.x * blockDim.x + threadIdx.x;
    if (i >= n) return;

    const float inv3 = 1.0f / 3.0f;
    float cx = (coords9[i*9+0] + coords9[i*9+3] + coords9[i*9+6]) * inv3;
    float cy = (coords9[i*9+1] + coords9[i*9+4] + coords9[i*9+7]) * inv3;
    float cz = (coords9[i*9+2] + coords9[i*9+5] + coords9[i*9+8]) * inv3;
    g_cent[i*3+0] = cx; g_cent[i*3+1] = cy; g_cent[i*3+2] = cz;

    float h[32];
    #pragma unroll
    for (int j = 0; j < 32; j++) {
        float v = cx*pe_w[j] + cy*pe_w[32+j] + cz*pe_w[64+j] + pe_b[j];
        // exact GELU
        h[j] = 0.5f * v * (1.0f + erff(v * 0.70710678118654752f));
    }
    float mu = 0.f;
    #pragma unroll
    for (int j = 0; j < 32; j++) mu += h[j];
    mu *= (1.0f/32.0f);
    float var = 0.f;
    #pragma unroll
    for (int j = 0; j < 32; j++) { float d = h[j]-mu; var += d*d; }
    var *= (1.0f/32.0f);
    float inv = rsqrtf(var + 1e-5f);

    // pos_enhanced: first 96 = x + prompt, last 32 = pe
    #pragma unroll 4
    for (int c = 0; c < 96; c++) g_pos[i*EMB + c] = x[i*EMB + c] + prompt[c];
    #pragma unroll
    for (int j = 0; j < 32; j++)
        g_pos[i*EMB + 96 + j] = (h[j]-mu)*inv*pe_g[j] + pe_bt[j];
}

// ---------------------------------------------------------------------------
// Stage 2: top-K nearest neighbors by squared centroid distance
// One block per row; squared distances in shared; 32x iterative argmin.
// ---------------------------------------------------------------------------
__global__ __launch_bounds__(256) void topk_kernel(int n)
{
    __shared__ float s_d[NMAX];
    __shared__ float rv[8];
    __shared__ int   ri[8];

    int i = blockIdx.x;
    int tid = threadIdx.x;
    float cx = g_cent[i*3+0], cy = g_cent[i*3+1], cz = g_cent[i*3+2];

    for (int j = tid; j < NMAX; j += 256) {
        float d = 3.4e38f;
        if (j < n) {
            float dx = g_cent[j*3+0] - cx;
            float dy = g_cent[j*3+1] - cy;
            float dz = g_cent[j*3+2] - cz;
            d = dx*dx + dy*dy + dz*dz;
        }
        s_d[j] = d;
    }
    __syncthreads();

    for (int it = 0; it < KNBR; it++) {
        float bv = 3.4e38f; int bi = 0x7fffffff;
        #pragma unroll
        for (int j = tid; j < NMAX; j += 256) {
            float v = s_d[j];
            if (v < bv) { bv = v; bi = j; }
        }
        #pragma unroll
        for (int off = 16; off; off >>= 1) {
            float ov = __shfl_down_sync(0xffffffffu, bv, off);
            int   oi = __shfl_down_sync(0xffffffffu, bi, off);
            if (ov < bv || (ov == bv && oi < bi)) { bv = ov; bi = oi; }
        }
        if ((tid & 31) == 0) { rv[tid >> 5] = bv; ri[tid >> 5] = bi; }
        __syncthreads();
        if (tid == 0) {
            float best = rv[0]; int bidx = ri[0];
            #pragma unroll
            for (int w = 1; w < 8; w++)
                if (rv[w] < best || (rv[w] == best && ri[w] < bidx)) { best = rv[w]; bidx = ri[w]; }
            g_nbr[i*KNBR + it] = bidx;
            s_d[bidx] = 3.4e38f;
        }
        __syncthreads();
    }
}

// ---------------------------------------------------------------------------
// Shared-tiled GEMM body: C[r][c] = dot(A[r,:128], W[c,:128]) + bias[c]
// A: n x 128, W: M x 128 row-major. Block: 16 rows x 64 cols, 256 threads.
// ---------------------------------------------------------------------------
__device__ __forceinline__ void gemm_body(
    const float* __restrict__ A, const float* __restrict__ W,
    const float* __restrict__ bias, float* __restrict__ C,
    int n, int M, bool do_sanitize)
{
    __shared__ float As[16][128];
    __shared__ float Wt[128][65];   // transposed: Wt[k][col]

    int row0 = blockIdx.y * 16;
    int col0 = blockIdx.x * 64;
    int tid = threadIdx.x;

    for (int idx = tid; idx < 16*128; idx += 256) {
        int r = idx >> 7, c = idx & 127;
        int gr = row0 + r;
        As[r][c] = (gr < n) ? A[gr*128 + c] : 0.f;
    }
    for (int idx = tid; idx < 64*128; idx += 256) {
        int r = idx >> 7, c = idx & 127;          // r = output col within tile
        Wt[c][r] = W[(col0 + r)*128 + c];
    }
    __syncthreads();

    int col = tid & 63;
    int rg  = tid >> 6;   // 0..3 -> rows rg*4 .. rg*4+3
    float a0 = 0.f, a1 = 0.f, a2 = 0.f, a3 = 0.f;
    #pragma unroll 8
    for (int k = 0; k < 128; k++) {
        float wv = Wt[k][col];
        a0 += As[rg*4+0][k] * wv;
        a1 += As[rg*4+1][k] * wv;
        a2 += As[rg*4+2][k] * wv;
        a3 += As[rg*4+3][k] * wv;
    }
    float b = bias[col0 + col];
    float acc[4] = {a0, a1, a2, a3};
    #pragma unroll
    for (int rr = 0; rr < 4; rr++) {
        int gr = row0 + rg*4 + rr;
        if (gr < n) {
            float v = acc[rr] + b;
            if (do_sanitize) {
                if (isnan(v)) v = 0.f;
                v = fminf(fmaxf(v, -1e4f), 1e4f);
            }
            C[gr*M + col0 + col] = v;
        }
    }
}

__global__ __launch_bounds__(256) void qkv_gemm_kernel(
    const float* __restrict__ W, const float* __restrict__ b, int n)
{
    gemm_body(g_pos, W, b, g_qkv, n, 3*EMB, false);
}

__global__ __launch_bounds__(256) void out_gemm_kernel(
    const float* __restrict__ W, const float* __restrict__ b,
    float* __restrict__ C, int n)
{
    gemm_body(g_o, W, b, C, n, EMB, true);
}

// ---------------------------------------------------------------------------
// Stage 4: sparse multi-head attention over the 32 neighbors.
// Block per node, warp per head (8 warps), lane per neighbor.
// Masked (non-neighbor) entries underflow to exactly 0 in the reference
// softmax (exp(-1e9-...) == 0.0f), so restricting to the K neighbors is exact.
// ---------------------------------------------------------------------------
__global__ __launch_bounds__(256) void attn_kernel(int n)
{
    __shared__ float s_k[KNBR][129];
    __shared__ float s_v[KNBR][129];
    __shared__ float s_q[128];
    __shared__ float s_p[NHEAD][KNBR];

    int i = blockIdx.x;
    int tid = threadIdx.x;

    if (tid < 128) s_q[tid] = g_qkv[i*384 + tid];
    for (int idx = tid; idx < KNBR*128; idx += 256) {
        int jj = idx >> 7, c = idx & 127;
        int r = g_nbr[i*KNBR + jj];
        s_k[jj][c] = g_qkv[r*384 + 128 + c];
        s_v[jj][c] = g_qkv[r*384 + 256 + c];
    }
    __syncthreads();

    int h = tid >> 5;   // head
    int l = tid & 31;   // neighbor
    float s = 0.f;
    #pragma unroll
    for (int d = 0; d < DHEAD; d++)
        s += s_q[h*DHEAD + d] * s_k[l][h*DHEAD + d];
    s *= 0.25f;   // 1/sqrt(16)

    float m = s;
    #pragma unroll
    for (int off = 16; off; off >>= 1)
        m = fmaxf(m, __shfl_xor_sync(0xffffffffu, m, off));
    float p = expf(s - m);
    float den = p;
    #pragma unroll
    for (int off = 16; off; off >>= 1)
        den += __shfl_xor_sync(0xffffffffu, den, off);
    s_p[h][l] = p / den;
    __syncthreads();

    if (tid < 128) {
        int hh = tid >> 4, d = tid & 15;
        float o = 0.f;
        #pragma unroll
        for (int j = 0; j < KNBR; j++)
            o += s_p[hh][j] * s_v[j][hh*DHEAD + d];
        g_o[i*EMB + tid] = o;
    }
}

// ---------------------------------------------------------------------------
extern "C" void kernel_launch(void* const* d_in, const int* in_sizes, int n_in,
                              void* d_out, int out_size)
{
    const float* x       = (const float*)d_in[0];
    const float* coords9 = (const float*)d_in[1];
    const float* prompt  = (const float*)d_in[2];
    const float* pe_w    = (const float*)d_in[3];
    const float* pe_b    = (const float*)d_in[4];
    const float* pe_g    = (const float*)d_in[5];
    const float* pe_bt   = (const float*)d_in[6];
    const float* in_w    = (const float*)d_in[7];
    const float* in_b    = (const float*)d_in[8];
    const float* out_w   = (const float*)d_in[9];
    const float* out_b   = (const float*)d_in[10];
    float* out = (float*)d_out;

    int n = in_sizes[0] / EMB;   // 2000

    prep_kernel<<<(n + 127) / 128, 128>>>(x, coords9, prompt, pe_w, pe_b, pe_g, pe_bt, n);
    topk_kernel<<<n, 256>>>(n);
    qkv_gemm_kernel<<<dim3((3*EMB)/64, (n + 15) / 16), 256>>>(in_w, in_b, n);
    attn_kernel<<<n, 256>>>(n);
    out_gemm_kernel<<<dim3(EMB/64, (n + 15) / 16), 256>>>(out_w, out_b, out, n);
}

// round 2
// speedup vs baseline: 1.0586x; 1.0586x over previous
#include <cuda_runtime.h>
#include <cuda_bf16.h>
#include <math.h>

#define EMB 128
#define NHEAD 8
#define DHEAD 16
#define KNBR 32
#define NMAX 2048
#define BIGF 3.4e38f

// Scratch (no cudaMalloc allowed)
__device__ float g_cent[NMAX * 3];
__device__ float g_pos [NMAX * EMB];
__device__ float g_qkv [NMAX * 3 * EMB];
__device__ int   g_nbr [NMAX * KNBR];
__device__ float g_o   [NMAX * EMB];

// ---------------------------------------------------------------------------
// Stage 1: warp-per-node prep. Centroid, PE = LN(GELU(cent@pe_w)), pos_enhanced.
// Coalesced copy of x+prompt (lane-strided), warp-shuffle LayerNorm.
// ---------------------------------------------------------------------------
__global__ __launch_bounds__(128) void prep_kernel(
    const float* __restrict__ x, const float* __restrict__ coords9,
    const float* __restrict__ prompt,
    const float* __restrict__ pe_w, const float* __restrict__ pe_b,
    const float* __restrict__ pe_g, const float* __restrict__ pe_bt, int n)
{
    int warp = threadIdx.x >> 5;
    int lane = threadIdx.x & 31;
    int i = blockIdx.x * 4 + warp;
    if (i >= n) return;

    const float inv3 = 1.0f / 3.0f;
    float cx = (coords9[i*9+0] + coords9[i*9+3] + coords9[i*9+6]) * inv3;
    float cy = (coords9[i*9+1] + coords9[i*9+4] + coords9[i*9+7]) * inv3;
    float cz = (coords9[i*9+2] + coords9[i*9+5] + coords9[i*9+8]) * inv3;
    if (lane == 0) {
        g_cent[i*3+0] = cx; g_cent[i*3+1] = cy; g_cent[i*3+2] = cz;
    }

    // PE: one lane per output channel j
    int j = lane;
    float v = cx*pe_w[j] + cy*pe_w[32+j] + cz*pe_w[64+j] + pe_b[j];
    float h = 0.5f * v * (1.0f + erff(v * 0.70710678118654752f));

    // warp LayerNorm over 32 channels
    float s = h, s2 = h*h;
    #pragma unroll
    for (int off = 16; off; off >>= 1) {
        s  += __shfl_xor_sync(0xffffffffu, s,  off);
        s2 += __shfl_xor_sync(0xffffffffu, s2, off);
    }
    float mu  = s * (1.0f/32.0f);
    float var = s2 * (1.0f/32.0f) - mu*mu;
    float inv = rsqrtf(var + 1e-5f);

    // coalesced copy of first 96 channels
    #pragma unroll
    for (int c = lane; c < 96; c += 32)
        g_pos[i*EMB + c] = x[i*EMB + c] + prompt[c];
    g_pos[i*EMB + 96 + j] = (h - mu) * inv * pe_g[j] + pe_bt[j];
}

// ---------------------------------------------------------------------------
// Stage 2: top-K via barrier-free warp-local selection + single-warp merge.
// Each of 8 warps holds 256 distances in registers (8/lane) and extracts its
// top-32 with shfl-only argmin. Warp 0 then merges the 256 candidates.
// Tie-break on equal distance: lower index (matches jax top_k).
// ---------------------------------------------------------------------------
__global__ __launch_bounds__(256) void topk_kernel(int n)
{
    __shared__ float c_d[256];
    __shared__ int   c_i[256];

    int i    = blockIdx.x;
    int tid  = threadIdx.x;
    int warp = tid >> 5;
    int lane = tid & 31;

    float cx = g_cent[i*3+0], cy = g_cent[i*3+1], cz = g_cent[i*3+2];

    float dv[8]; int di[8];
    #pragma unroll
    for (int u = 0; u < 8; u++) {
        int j = warp*256 + u*32 + lane;
        float d = BIGF;
        if (j < n) {
            float dx = g_cent[j*3+0] - cx;
            float dy = g_cent[j*3+1] - cy;
            float dz = g_cent[j*3+2] - cz;
            d = dx*dx + dy*dy + dz*dz;
        }
        dv[u] = d; di[u] = j;
    }

    // warp-local top-32 (sorted), no barriers
    #pragma unroll 1
    for (int it = 0; it < KNBR; it++) {
        float bv = dv[0]; int bi = di[0]; int bu = 0;
        #pragma unroll
        for (int u = 1; u < 8; u++)
            if (dv[u] < bv || (dv[u] == bv && di[u] < bi)) { bv = dv[u]; bi = di[u]; bu = u; }
        float rv = bv; int ri = bi;
        #pragma unroll
        for (int off = 16; off; off >>= 1) {
            float ov = __shfl_xor_sync(0xffffffffu, rv, off);
            int   oi = __shfl_xor_sync(0xffffffffu, ri, off);
            if (ov < rv || (ov == rv && oi < ri)) { rv = ov; ri = oi; }
        }
        if (bi == ri) dv[bu] = BIGF;   // unique owner invalidates
        if (lane == 0) { c_d[warp*32 + it] = rv; c_i[warp*32 + it] = ri; }
    }
    __syncthreads();

    // warp 0 merges 256 candidates
    if (warp == 0) {
        float mv[8]; int mi[8];
        #pragma unroll
        for (int u = 0; u < 8; u++) { mv[u] = c_d[u*32 + lane]; mi[u] = c_i[u*32 + lane]; }
        #pragma unroll 1
        for (int it = 0; it < KNBR; it++) {
            float bv = mv[0]; int bi = mi[0]; int bu = 0;
            #pragma unroll
            for (int u = 1; u < 8; u++)
                if (mv[u] < bv || (mv[u] == bv && mi[u] < bi)) { bv = mv[u]; bi = mi[u]; bu = u; }
            float rv = bv; int ri = bi;
            #pragma unroll
            for (int off = 16; off; off >>= 1) {
                float ov = __shfl_xor_sync(0xffffffffu, rv, off);
                int   oi = __shfl_xor_sync(0xffffffffu, ri, off);
                if (ov < rv || (ov == rv && oi < ri)) { rv = ov; ri = oi; }
            }
            if (bi == ri) mv[bu] = BIGF;
            if (lane == 0) g_nbr[i*KNBR + it] = ri;
        }
    }
}

// ---------------------------------------------------------------------------
// Register-tiled GEMM: C[r][c] = dot(A[r,:128], W[c,:128]) + bias[c]
// Block tile 16 rows x 64 cols, 256 threads, 2x2 outputs per thread.
// A-frag reads are warp-broadcast; W smem padded to 132 floats/row -> no conflicts.
// ---------------------------------------------------------------------------
__device__ __forceinline__ float dot4(float4 a, float4 b) {
    return a.x*b.x + a.y*b.y + a.z*b.z + a.w*b.w;
}

__device__ __forceinline__ void gemm_body(
    const float* __restrict__ A, const float* __restrict__ W,
    const float* __restrict__ bias, float* __restrict__ C,
    int n, int M, bool do_sanitize)
{
    __shared__ float As[16 * 128];      // 8 KB
    __shared__ float Ws[64 * 132];      // 33.8 KB (padded rows)

    int row0 = blockIdx.y * 16;
    int col0 = blockIdx.x * 64;
    int tid  = threadIdx.x;

    // load A tile (vectorized, zero-fill OOB rows)
    #pragma unroll
    for (int u = 0; u < 2; u++) {
        int lin = tid + u*256;
        int r = lin >> 5, c4 = lin & 31;
        int gr = row0 + r;
        float4 av = make_float4(0.f,0.f,0.f,0.f);
        if (gr < n) av = ((const float4*)(A + (size_t)gr*128))[c4];
        ((float4*)(As + r*128))[c4] = av;
    }
    // load W tile (vectorized)
    #pragma unroll
    for (int u = 0; u < 8; u++) {
        int lin = tid + u*256;
        int cc = lin >> 5, k4 = lin & 31;
        float4 wv = ((const float4*)(W + (size_t)(col0 + cc)*128))[k4];
        ((float4*)(Ws + cc*132))[k4] = wv;
    }
    __syncthreads();

    int tx = tid & 31;       // cols tx, tx+32
    int ty = tid >> 5;       // rows ty*2, ty*2+1
    const float4* a0p = (const float4*)(As + (ty*2+0)*128);
    const float4* a1p = (const float4*)(As + (ty*2+1)*128);
    const float4* w0p = (const float4*)(Ws + tx*132);
    const float4* w1p = (const float4*)(Ws + (tx+32)*132);

    float acc00 = 0.f, acc01 = 0.f, acc10 = 0.f, acc11 = 0.f;
    #pragma unroll
    for (int k4 = 0; k4 < 32; k4++) {
        float4 a0 = a0p[k4], a1 = a1p[k4];
        float4 w0 = w0p[k4], w1 = w1p[k4];
        acc00 += dot4(a0, w0);
        acc01 += dot4(a0, w1);
        acc10 += dot4(a1, w0);
        acc11 += dot4(a1, w1);
    }

    int c0 = col0 + tx, c1 = col0 + tx + 32;
    float b0 = bias[c0], b1 = bias[c1];
    float vals[2][2] = {{acc00 + b0, acc01 + b1}, {acc10 + b0, acc11 + b1}};
    #pragma unroll
    for (int r = 0; r < 2; r++) {
        int gr = row0 + ty*2 + r;
        if (gr < n) {
            #pragma unroll
            for (int c = 0; c < 2; c++) {
                float v = vals[r][c];
                if (do_sanitize) {
                    if (isnan(v)) v = 0.f;
                    v = fminf(fmaxf(v, -1e4f), 1e4f);
                }
                C[(size_t)gr*M + (c ? c1 : c0)] = v;
            }
        }
    }
}

__global__ __launch_bounds__(256) void qkv_gemm_kernel(
    const float* __restrict__ W, const float* __restrict__ b, int n)
{
    gemm_body(g_pos, W, b, g_qkv, n, 3*EMB, false);
}

__global__ __launch_bounds__(256) void out_gemm_kernel(
    const float* __restrict__ W, const float* __restrict__ b,
    float* __restrict__ C, int n)
{
    gemm_body(g_o, W, b, C, n, EMB, true);
}

// ---------------------------------------------------------------------------
// Stage 4: sparse attention over 32 neighbors. Block per node.
// Scores read K straight from L2 (float4 gathers); only V staged in smem.
// One barrier. Masked entries underflow to exactly 0 in reference softmax,
// so restricting to K neighbors is exact.
// ---------------------------------------------------------------------------
__global__ __launch_bounds__(256) void attn_kernel(int n)
{
    __shared__ float s_v[KNBR][EMB];     // 16 KB, conflict-free by construction
    __shared__ float s_q[EMB];
    __shared__ float s_p[NHEAD][KNBR + 1];
    __shared__ int   s_idx[KNBR];

    int i   = blockIdx.x;
    int tid = threadIdx.x;

    if (tid < 32) s_idx[tid] = g_nbr[i*KNBR + tid];
    if (tid >= 128) s_q[tid - 128] = g_qkv[i*384 + (tid - 128)];
    __syncthreads();

    // gather V rows (warp per row, float4)
    {
        int c4 = tid & 31;
        #pragma unroll
        for (int u = 0; u < 4; u++) {
            int jj = (tid >> 5) + u*8;
            const float4* src = (const float4*)(g_qkv + (size_t)s_idx[jj]*384 + 256);
            ((float4*)s_v[jj])[c4] = src[c4];
        }
    }

    // scores: warp h, lane l = neighbor
    int h = tid >> 5, l = tid & 31;
    const float4* kp = (const float4*)(g_qkv + (size_t)s_idx[l]*384 + 128 + h*DHEAD);
    const float4* qp = (const float4*)(s_q + h*DHEAD);
    float s = 0.f;
    #pragma unroll
    for (int u = 0; u < 4; u++) s += dot4(qp[u], kp[u]);
    s *= 0.25f;   // 1/sqrt(16)

    float m = s;
    #pragma unroll
    for (int off = 16; off; off >>= 1)
        m = fmaxf(m, __shfl_xor_sync(0xffffffffu, m, off));
    float p = expf(s - m);
    float den = p;
    #pragma unroll
    for (int off = 16; off; off >>= 1)
        den += __shfl_xor_sync(0xffffffffu, den, off);
    s_p[h][l] = p / den;
    __syncthreads();

    if (tid < 128) {
        int hh = tid >> 4, d = tid & 15;
        float o = 0.f;
        #pragma unroll
        for (int j = 0; j < KNBR; j++)
            o += s_p[hh][j] * s_v[j][hh*DHEAD + d];
        g_o[i*EMB + tid] = o;
    }
}

// ---------------------------------------------------------------------------
extern "C" void kernel_launch(void* const* d_in, const int* in_sizes, int n_in,
                              void* d_out, int out_size)
{
    const float* x       = (const float*)d_in[0];
    const float* coords9 = (const float*)d_in[1];
    const float* prompt  = (const float*)d_in[2];
    const float* pe_w    = (const float*)d_in[3];
    const float* pe_b    = (const float*)d_in[4];
    const float* pe_g    = (const float*)d_in[5];
    const float* pe_bt   = (const float*)d_in[6];
    const float* in_w    = (const float*)d_in[7];
    const float* in_b    = (const float*)d_in[8];
    const float* out_w   = (const float*)d_in[9];
    const float* out_b   = (const float*)d_in[10];
    float* out = (float*)d_out;

    int n = in_sizes[0] / EMB;   // 2000

    prep_kernel<<<(n + 3) / 4, 128>>>(x, coords9, prompt, pe_w, pe_b, pe_g, pe_bt, n);
    topk_kernel<<<n, 256>>>(n);
    qkv_gemm_kernel<<<dim3((3*EMB)/64, (n + 15) / 16), 256>>>(in_w, in_b, n);
    attn_kernel<<<n, 256>>>(n);
    out_gemm_kernel<<<dim3(EMB/64, (n + 15) / 16), 256>>>(out_w, out_b, out, n);
}

// round 3
// speedup vs baseline: 1.7573x; 1.6599x over previous
#include <cuda_runtime.h>
#include <cuda_bf16.h>
#include <math.h>

#define EMB 128
#define NHEAD 8
#define DHEAD 16
#define KNBR 32
#define NMAX 2048
#define TKW 4          // queries (warps) per topk block

// Scratch (no cudaMalloc allowed)
__device__ float g_cent[NMAX * 3];
__device__ float g_pos [NMAX * EMB];
__device__ float g_qkv [NMAX * 3 * EMB];
__device__ int   g_nbr [NMAX * KNBR];
__device__ float g_o   [NMAX * EMB];

__device__ __forceinline__ float dot4(float4 a, float4 b) {
    return a.x*b.x + a.y*b.y + a.z*b.z + a.w*b.w;
}

// ---------------------------------------------------------------------------
// Stage 1: warp-per-node prep (centroid, PE = LN(GELU(cent@pe_w)), pos_enhanced)
// ---------------------------------------------------------------------------
__global__ __launch_bounds__(128) void prep_kernel(
    const float* __restrict__ x, const float* __restrict__ coords9,
    const float* __restrict__ prompt,
    const float* __restrict__ pe_w, const float* __restrict__ pe_b,
    const float* __restrict__ pe_g, const float* __restrict__ pe_bt, int n)
{
    int warp = threadIdx.x >> 5;
    int lane = threadIdx.x & 31;
    int i = blockIdx.x * 4 + warp;
    if (i >= n) return;

    const float inv3 = 1.0f / 3.0f;
    float cx = (coords9[i*9+0] + coords9[i*9+3] + coords9[i*9+6]) * inv3;
    float cy = (coords9[i*9+1] + coords9[i*9+4] + coords9[i*9+7]) * inv3;
    float cz = (coords9[i*9+2] + coords9[i*9+5] + coords9[i*9+8]) * inv3;
    if (lane == 0) {
        g_cent[i*3+0] = cx; g_cent[i*3+1] = cy; g_cent[i*3+2] = cz;
    }

    int j = lane;
    float v = cx*pe_w[j] + cy*pe_w[32+j] + cz*pe_w[64+j] + pe_b[j];
    float h = 0.5f * v * (1.0f + erff(v * 0.70710678118654752f));

    float s = h, s2 = h*h;
    #pragma unroll
    for (int off = 16; off; off >>= 1) {
        s  += __shfl_xor_sync(0xffffffffu, s,  off);
        s2 += __shfl_xor_sync(0xffffffffu, s2, off);
    }
    float mu  = s * (1.0f/32.0f);
    float var = s2 * (1.0f/32.0f) - mu*mu;
    float inv = rsqrtf(var + 1e-5f);

    #pragma unroll
    for (int c = lane; c < 96; c += 32)
        g_pos[i*EMB + c] = x[i*EMB + c] + prompt[c];
    g_pos[i*EMB + 96 + j] = (h - mu) * inv * pe_g[j] + pe_bt[j];
}

// ---------------------------------------------------------------------------
// Stage 2: top-K via exact 4-level radix select on uint(d^2) keys.
// Warp per query, keys in warp-private shared. Output order is irrelevant
// (the reference attention mask is a SET of kept positions); ties at the
// rank-32 boundary broken by lower index (ascending-j emission), matching jax.
// ---------------------------------------------------------------------------
__global__ __launch_bounds__(128) void topk_kernel(int n)
{
    __shared__ unsigned s_key [TKW][NMAX];   // 32 KB
    __shared__ unsigned s_hist[TKW][256];    // 4 KB

    int warp = threadIdx.x >> 5;
    int lane = threadIdx.x & 31;
    int i = blockIdx.x * TKW + warp;
    if (i >= n) return;   // warp-private everything; no block syncs below

    unsigned* key  = s_key[warp];
    unsigned* hist = s_hist[warp];

    float cx = g_cent[i*3+0], cy = g_cent[i*3+1], cz = g_cent[i*3+2];

    #pragma unroll
    for (int u = 0; u < 8; u++) hist[u*32 + lane] = 0u;
    __syncwarp();

    // Pass 0: keys + level-0 histogram (top byte). Pads get 0xFFFFFFFF (bin 255,
    // unreachable: finite d^2 keys have top byte <= 0x7F).
    #pragma unroll 2
    for (int u = 0; u < NMAX/32; u++) {
        int j = u*32 + lane;
        unsigned k = 0xFFFFFFFFu;
        if (j < n) {
            float dx = g_cent[j*3+0] - cx;
            float dy = g_cent[j*3+1] - cy;
            float dz = g_cent[j*3+2] - cz;
            k = __float_as_uint(dx*dx + dy*dy + dz*dz);
        }
        key[j] = k;
        int b = k >> 24;
        unsigned grp = __match_any_sync(0xffffffffu, b);
        if ((grp & ((1u << lane) - 1u)) == 0u)      // group leader
            atomicAdd(&hist[b], (unsigned)__popc(grp));
    }
    __syncwarp();

    // 4-level radix descent: after it, Tkey = exact rank-32 key,
    // rem = #elements equal to Tkey that must still be taken.
    unsigned rem  = KNBR;
    unsigned Tkey = 0u;
    #pragma unroll 1
    for (int level = 0; level < 4; level++) {
        int shift = 24 - level*8;

        // scan 256 bins: find bin b* with cum_excl < rem <= cum_incl
        unsigned h[8]; unsigned lsum = 0u;
        #pragma unroll
        for (int u = 0; u < 8; u++) { h[u] = hist[lane*8 + u]; lsum += h[u]; }
        unsigned incl = lsum;
        #pragma unroll
        for (int off = 1; off < 32; off <<= 1) {
            unsigned v = __shfl_up_sync(0xffffffffu, incl, off);
            if (lane >= off) incl += v;
        }
        unsigned cum = incl - lsum;    // exclusive prefix at this lane's first bin
        int bloc = -1; unsigned cb_loc = 0u;
        #pragma unroll
        for (int u = 0; u < 8; u++) {
            if (cum < rem && cum + h[u] >= rem) { bloc = lane*8 + u; cb_loc = cum; }
            cum += h[u];
        }
        unsigned bal = __ballot_sync(0xffffffffu, bloc >= 0);
        int src = __ffs(bal) - 1;
        int bstar   = __shfl_sync(0xffffffffu, bloc,   src);
        unsigned cb = __shfl_sync(0xffffffffu, cb_loc, src);
        rem -= cb;
        Tkey |= ((unsigned)bstar) << shift;

        if (level < 3) {
            __syncwarp();
            #pragma unroll
            for (int u = 0; u < 8; u++) hist[u*32 + lane] = 0u;
            __syncwarp();
            unsigned pref = Tkey >> shift;
            #pragma unroll 2
            for (int u = 0; u < NMAX/32; u++) {
                unsigned k = key[u*32 + lane];
                if ((k >> shift) == pref)
                    atomicAdd(&hist[(k >> (shift - 8)) & 0xFFu], 1u);
            }
            __syncwarp();
        }
    }

    // Emission: all keys < T, plus first `rem` keys == T in ascending j.
    unsigned T = Tkey;
    unsigned base = 0u, remq = rem;
    int out_base = i * KNBR;
    #pragma unroll 2
    for (int u = 0; u < NMAX/32; u++) {
        unsigned k = key[u*32 + lane];
        unsigned blt = __ballot_sync(0xffffffffu, k < T);
        unsigned beq = __ballot_sync(0xffffffffu, k == T);
        if (k < T) {
            int pos = base + __popc(blt & ((1u << lane) - 1u));
            g_nbr[out_base + pos] = u*32 + lane;
        }
        base += __popc(blt);
        if (beq) {
            unsigned neq  = __popc(beq);
            unsigned take = remq < neq ? remq : neq;
            if (k == T) {
                unsigned rank = __popc(beq & ((1u << lane) - 1u));
                if (rank < take) g_nbr[out_base + base + rank] = u*32 + lane;
            }
            base += take;
            remq -= take;
        }
    }
}

// ---------------------------------------------------------------------------
// Register-tiled GEMM: C[r][c] = dot(A[r,:128], W[c,:128]) + bias[c]
// Block tile 16 rows x 64 cols, 256 threads, 2x2 outputs per thread.
// ---------------------------------------------------------------------------
__device__ __forceinline__ void gemm_body(
    const float* __restrict__ A, const float* __restrict__ W,
    const float* __restrict__ bias, float* __restrict__ C,
    int n, int M, bool do_sanitize)
{
    __shared__ float As[16 * 128];
    __shared__ float Ws[64 * 132];

    int row0 = blockIdx.y * 16;
    int col0 = blockIdx.x * 64;
    int tid  = threadIdx.x;

    #pragma unroll
    for (int u = 0; u < 2; u++) {
        int lin = tid + u*256;
        int r = lin >> 5, c4 = lin & 31;
        int gr = row0 + r;
        float4 av = make_float4(0.f,0.f,0.f,0.f);
        if (gr < n) av = ((const float4*)(A + (size_t)gr*128))[c4];
        ((float4*)(As + r*128))[c4] = av;
    }
    #pragma unroll
    for (int u = 0; u < 8; u++) {
        int lin = tid + u*256;
        int cc = lin >> 5, k4 = lin & 31;
        float4 wv = ((const float4*)(W + (size_t)(col0 + cc)*128))[k4];
        ((float4*)(Ws + cc*132))[k4] = wv;
    }
    __syncthreads();

    int tx = tid & 31;
    int ty = tid >> 5;
    const float4* a0p = (const float4*)(As + (ty*2+0)*128);
    const float4* a1p = (const float4*)(As + (ty*2+1)*128);
    const float4* w0p = (const float4*)(Ws + tx*132);
    const float4* w1p = (const float4*)(Ws + (tx+32)*132);

    float acc00 = 0.f, acc01 = 0.f, acc10 = 0.f, acc11 = 0.f;
    #pragma unroll
    for (int k4 = 0; k4 < 32; k4++) {
        float4 a0 = a0p[k4], a1 = a1p[k4];
        float4 w0 = w0p[k4], w1 = w1p[k4];
        acc00 += dot4(a0, w0);
        acc01 += dot4(a0, w1);
        acc10 += dot4(a1, w0);
        acc11 += dot4(a1, w1);
    }

    int c0 = col0 + tx, c1 = col0 + tx + 32;
    float b0 = bias[c0], b1 = bias[c1];
    float vals[2][2] = {{acc00 + b0, acc01 + b1}, {acc10 + b0, acc11 + b1}};
    #pragma unroll
    for (int r = 0; r < 2; r++) {
        int gr = row0 + ty*2 + r;
        if (gr < n) {
            #pragma unroll
            for (int c = 0; c < 2; c++) {
                float v = vals[r][c];
                if (do_sanitize) {
                    if (isnan(v)) v = 0.f;
                    v = fminf(fmaxf(v, -1e4f), 1e4f);
                }
                C[(size_t)gr*M + (c ? c1 : c0)] = v;
            }
        }
    }
}

__global__ __launch_bounds__(256) void qkv_gemm_kernel(
    const float* __restrict__ W, const float* __restrict__ b, int n)
{
    gemm_body(g_pos, W, b, g_qkv, n, 3*EMB, false);
}

__global__ __launch_bounds__(256) void out_gemm_kernel(
    const float* __restrict__ W, const float* __restrict__ b,
    float* __restrict__ C, int n)
{
    gemm_body(g_o, W, b, C, n, EMB, true);
}

// ---------------------------------------------------------------------------
// Stage 4: sparse attention over 32 neighbors, 128 threads/block, 1 barrier.
// Neighbor indices live in lane registers (shfl-distributed); q via broadcast
// LDG; K read straight from L2; only V staged in smem.
// ---------------------------------------------------------------------------
__global__ __launch_bounds__(128) void attn_kernel(int n)
{
    __shared__ float s_v[KNBR][EMB];          // 16 KB
    __shared__ float s_p[NHEAD][KNBR];

    int i    = blockIdx.x;
    int tid  = threadIdx.x;
    int w    = tid >> 5;
    int lane = tid & 31;

    int idx_l = g_nbr[i*KNBR + lane];

    // V gather: warp w loads rows w*8 .. w*8+7 (float4, conflict-free)
    #pragma unroll
    for (int u = 0; u < 8; u++) {
        int jj = w*8 + u;
        int r = __shfl_sync(0xffffffffu, idx_l, jj);
        const float4* src = (const float4*)(g_qkv + (size_t)r*384 + 256);
        ((float4*)s_v[jj])[lane] = src[lane];
    }

    // scores: warp w -> heads 2w, 2w+1; lane = neighbor
    const float4* kbase = (const float4*)(g_qkv + (size_t)idx_l*384 + 128);
    const float4* qbase = (const float4*)(g_qkv + (size_t)i*384);
    #pragma unroll
    for (int hh = 0; hh < 2; hh++) {
        int h = 2*w + hh;
        float4 q0 = qbase[h*4+0], q1 = qbase[h*4+1], q2 = qbase[h*4+2], q3 = qbase[h*4+3];
        float4 k0 = kbase[h*4+0], k1 = kbase[h*4+1], k2 = kbase[h*4+2], k3 = kbase[h*4+3];
        float s = dot4(q0,k0) + dot4(q1,k1) + dot4(q2,k2) + dot4(q3,k3);
        s *= 0.25f;   // 1/sqrt(16)

        float m = s;
        #pragma unroll
        for (int off = 16; off; off >>= 1)
            m = fmaxf(m, __shfl_xor_sync(0xffffffffu, m, off));
        float p = expf(s - m);
        float den = p;
        #pragma unroll
        for (int off = 16; off; off >>= 1)
            den += __shfl_xor_sync(0xffffffffu, den, off);
        s_p[h][lane] = p / den;
    }
    __syncthreads();

    // output: thread t -> (head t>>4, dim t&15)
    int hh = tid >> 4, d = tid & 15;
    float o = 0.f;
    #pragma unroll
    for (int j = 0; j < KNBR; j++)
        o += s_p[hh][j] * s_v[j][hh*DHEAD + d];
    g_o[i*EMB + tid] = o;
}

// ---------------------------------------------------------------------------
extern "C" void kernel_launch(void* const* d_in, const int* in_sizes, int n_in,
                              void* d_out, int out_size)
{
    const float* x       = (const float*)d_in[0];
    const float* coords9 = (const float*)d_in[1];
    const float* prompt  = (const float*)d_in[2];
    const float* pe_w    = (const float*)d_in[3];
    const float* pe_b    = (const float*)d_in[4];
    const float* pe_g    = (const float*)d_in[5];
    const float* pe_bt   = (const float*)d_in[6];
    const float* in_w    = (const float*)d_in[7];
    const float* in_b    = (const float*)d_in[8];
    const float* out_w   = (const float*)d_in[9];
    const float* out_b   = (const float*)d_in[10];
    float* out = (float*)d_out;

    int n = in_sizes[0] / EMB;   // 2000

    prep_kernel<<<(n + 3) / 4, 128>>>(x, coords9, prompt, pe_w, pe_b, pe_g, pe_bt, n);
    topk_kernel<<<(n + TKW - 1) / TKW, 128>>>(n);
    qkv_gemm_kernel<<<dim3((3*EMB)/64, (n + 15) / 16), 256>>>(in_w, in_b, n);
    attn_kernel<<<n, 128>>>(n);
    out_gemm_kernel<<<dim3(EMB/64, (n + 15) / 16), 256>>>(out_w, out_b, out, n);
}

// round 4
// speedup vs baseline: 2.3924x; 1.3614x over previous
#include <cuda_runtime.h>
#include <cuda_bf16.h>
#include <math.h>

#define EMB 128
#define NHEAD 8
#define DHEAD 16
#define KNBR 32
#define NMAX 2048

// Scratch (no cudaMalloc allowed)
__device__ float4 g_cent[NMAX];
__device__ float  g_pos [NMAX * EMB];
__device__ float  g_qkv [NMAX * 3 * EMB];
__device__ float  g_o   [NMAX * EMB];

__device__ __forceinline__ float dot4(float4 a, float4 b) {
    return a.x*b.x + a.y*b.y + a.z*b.z + a.w*b.w;
}

// ---------------------------------------------------------------------------
// Stage 1: warp-per-node prep (centroid, PE = LN(GELU(cent@pe_w)), pos_enhanced)
// ---------------------------------------------------------------------------
__global__ __launch_bounds__(128) void prep_kernel(
    const float* __restrict__ x, const float* __restrict__ coords9,
    const float* __restrict__ prompt,
    const float* __restrict__ pe_w, const float* __restrict__ pe_b,
    const float* __restrict__ pe_g, const float* __restrict__ pe_bt, int n)
{
    int warp = threadIdx.x >> 5;
    int lane = threadIdx.x & 31;
    int i = blockIdx.x * 4 + warp;
    if (i >= n) return;

    const float inv3 = 1.0f / 3.0f;
    float cx = (coords9[i*9+0] + coords9[i*9+3] + coords9[i*9+6]) * inv3;
    float cy = (coords9[i*9+1] + coords9[i*9+4] + coords9[i*9+7]) * inv3;
    float cz = (coords9[i*9+2] + coords9[i*9+5] + coords9[i*9+8]) * inv3;
    if (lane == 0) g_cent[i] = make_float4(cx, cy, cz, 0.f);

    int j = lane;
    float v = cx*pe_w[j] + cy*pe_w[32+j] + cz*pe_w[64+j] + pe_b[j];
    float h = 0.5f * v * (1.0f + erff(v * 0.70710678118654752f));

    float s = h, s2 = h*h;
    #pragma unroll
    for (int off = 16; off; off >>= 1) {
        s  += __shfl_xor_sync(0xffffffffu, s,  off);
        s2 += __shfl_xor_sync(0xffffffffu, s2, off);
    }
    float mu  = s * (1.0f/32.0f);
    float var = s2 * (1.0f/32.0f) - mu*mu;
    float inv = rsqrtf(var + 1e-5f);

    #pragma unroll
    for (int c = lane; c < 96; c += 32)
        g_pos[i*EMB + c] = x[i*EMB + c] + prompt[c];
    g_pos[i*EMB + 96 + j] = (h - mu) * inv * pe_g[j] + pe_bt[j];
}

// ---------------------------------------------------------------------------
// Register-tiled GEMM: C[r][c] = dot(A[r,:128], W[c,:128]) + bias[c]
// Block tile 16 rows x 64 cols, 256 threads, 2x2 outputs per thread.
// ---------------------------------------------------------------------------
__device__ __forceinline__ void gemm_body(
    const float* __restrict__ A, const float* __restrict__ W,
    const float* __restrict__ bias, float* __restrict__ C,
    int n, int M, bool do_sanitize)
{
    __shared__ float As[16 * 128];
    __shared__ float Ws[64 * 132];

    int row0 = blockIdx.y * 16;
    int col0 = blockIdx.x * 64;
    int tid  = threadIdx.x;

    #pragma unroll
    for (int u = 0; u < 2; u++) {
        int lin = tid + u*256;
        int r = lin >> 5, c4 = lin & 31;
        int gr = row0 + r;
        float4 av = make_float4(0.f,0.f,0.f,0.f);
        if (gr < n) av = ((const float4*)(A + (size_t)gr*128))[c4];
        ((float4*)(As + r*128))[c4] = av;
    }
    #pragma unroll
    for (int u = 0; u < 8; u++) {
        int lin = tid + u*256;
        int cc = lin >> 5, k4 = lin & 31;
        float4 wv = ((const float4*)(W + (size_t)(col0 + cc)*128))[k4];
        ((float4*)(Ws + cc*132))[k4] = wv;
    }
    __syncthreads();

    int tx = tid & 31;
    int ty = tid >> 5;
    const float4* a0p = (const float4*)(As + (ty*2+0)*128);
    const float4* a1p = (const float4*)(As + (ty*2+1)*128);
    const float4* w0p = (const float4*)(Ws + tx*132);
    const float4* w1p = (const float4*)(Ws + (tx+32)*132);

    float acc00 = 0.f, acc01 = 0.f, acc10 = 0.f, acc11 = 0.f;
    #pragma unroll
    for (int k4 = 0; k4 < 32; k4++) {
        float4 a0 = a0p[k4], a1 = a1p[k4];
        float4 w0 = w0p[k4], w1 = w1p[k4];
        acc00 += dot4(a0, w0);
        acc01 += dot4(a0, w1);
        acc10 += dot4(a1, w0);
        acc11 += dot4(a1, w1);
    }

    int c0 = col0 + tx, c1 = col0 + tx + 32;
    float b0 = bias[c0], b1 = bias[c1];
    float vals[2][2] = {{acc00 + b0, acc01 + b1}, {acc10 + b0, acc11 + b1}};
    #pragma unroll
    for (int r = 0; r < 2; r++) {
        int gr = row0 + ty*2 + r;
        if (gr < n) {
            #pragma unroll
            for (int c = 0; c < 2; c++) {
                float v = vals[r][c];
                if (do_sanitize) {
                    if (isnan(v)) v = 0.f;
                    v = fminf(fmaxf(v, -1e4f), 1e4f);
                }
                C[(size_t)gr*M + (c ? c1 : c0)] = v;
            }
        }
    }
}

__global__ __launch_bounds__(256) void qkv_gemm_kernel(
    const float* __restrict__ W, const float* __restrict__ b, int n)
{
    gemm_body(g_pos, W, b, g_qkv, n, 3*EMB, false);
}

__global__ __launch_bounds__(256) void out_gemm_kernel(
    const float* __restrict__ W, const float* __restrict__ b,
    float* __restrict__ C, int n)
{
    gemm_body(g_o, W, b, C, n, EMB, true);
}

// ---------------------------------------------------------------------------
// Fused top-K + sparse attention. One block (256 threads) per node.
// Phase A: exact 4-level radix select over uint(d^2) keys (block-wide,
//          256-bin smem histograms, warp-0 bin scan).
// Phase B: order-free emission of keys < T, ascending-index ties at T
//          (output SET is all that matters for the attention mask; ties at
//          the rank-32 boundary take lowest indices, matching jax top_k).
// Phase C: head-per-warp attention over the 32 selected neighbors.
// ---------------------------------------------------------------------------
__global__ __launch_bounds__(256) void fused_attn_kernel(int n)
{
    __shared__ unsigned s_key[NMAX];          // 8 KB
    __shared__ unsigned s_hist[256];          // 1 KB
    __shared__ float    s_v[KNBR][EMB];       // 16 KB
    __shared__ float    s_p[NHEAD][KNBR];
    __shared__ int      s_nbr[KNBR];
    __shared__ unsigned s_Tkey, s_rem;
    __shared__ int      s_cnt;

    int i    = blockIdx.x;
    int tid  = threadIdx.x;
    int w    = tid >> 5;
    int lane = tid & 31;

    // ---- Phase A: keys + level-0 histogram -------------------------------
    s_hist[tid] = 0u;
    if (tid == 0) { s_Tkey = 0u; s_rem = KNBR; s_cnt = 0; }
    __syncthreads();

    float4 c0 = g_cent[i];   // broadcast
    #pragma unroll
    for (int u = 0; u < NMAX/256; u++) {
        int j = tid + u*256;
        unsigned k = 0xFFFFFFFFu;   // pad: unreachable bin (finite keys < 0x7F800000)
        if (j < n) {
            float4 cj = g_cent[j];
            float dx = cj.x - c0.x, dy = cj.y - c0.y, dz = cj.z - c0.z;
            k = __float_as_uint(dx*dx + dy*dy + dz*dz);
        }
        s_key[j] = k;
        atomicAdd(&s_hist[k >> 24], 1u);
    }
    __syncthreads();

    // ---- radix descent: 4 levels of 8 bits -------------------------------
    #pragma unroll 1
    for (int level = 0; level < 4; level++) {
        int shift = 24 - level*8;

        if (tid < 32) {   // warp 0 scans 256 bins (8 per lane)
            unsigned h[8]; unsigned lsum = 0u;
            #pragma unroll
            for (int u = 0; u < 8; u++) { h[u] = s_hist[lane*8 + u]; lsum += h[u]; }
            unsigned incl = lsum;
            #pragma unroll
            for (int off = 1; off < 32; off <<= 1) {
                unsigned v = __shfl_up_sync(0xffffffffu, incl, off);
                if (lane >= off) incl += v;
            }
            unsigned cum = incl - lsum;
            unsigned rem = s_rem;
            int bloc = -1; unsigned cb_loc = 0u;
            #pragma unroll
            for (int u = 0; u < 8; u++) {
                if (cum < rem && cum + h[u] >= rem) { bloc = lane*8 + u; cb_loc = cum; }
                cum += h[u];
            }
            unsigned bal = __ballot_sync(0xffffffffu, bloc >= 0);
            int src = __ffs(bal) - 1;
            if (lane == src) {
                s_Tkey |= ((unsigned)bloc) << shift;
                s_rem   = rem - cb_loc;
            }
        }
        __syncthreads();

        if (level < 3) {
            unsigned pref = s_Tkey >> shift;
            s_hist[tid] = 0u;
            __syncthreads();
            #pragma unroll
            for (int u = 0; u < NMAX/256; u++) {
                unsigned k = s_key[tid + u*256];
                if ((k >> shift) == pref)
                    atomicAdd(&s_hist[(k >> (shift - 8)) & 0xFFu], 1u);
            }
            __syncthreads();
        }
    }

    // ---- Phase B: emission ----------------------------------------------
    unsigned T = s_Tkey;
    #pragma unroll
    for (int u = 0; u < NMAX/256; u++) {
        int j = tid + u*256;
        if (s_key[j] < T) {
            int p = atomicAdd(&s_cnt, 1);
            s_nbr[p] = j;
        }
    }
    __syncthreads();

    if (tid < 32) {   // warp 0: ties == T, ascending index
        int c = s_cnt;
        int need = KNBR - c;
        int pos = c;
        #pragma unroll 1
        for (int u = 0; u < NMAX/32 && need > 0; u++) {
            int j = u*32 + lane;
            unsigned k = s_key[j];
            unsigned beq = __ballot_sync(0xffffffffu, k == T);
            if (beq) {
                int neq  = __popc(beq);
                int take = need < neq ? need : neq;
                if (k == T) {
                    int rank = __popc(beq & ((1u << lane) - 1u));
                    if (rank < take) s_nbr[pos + rank] = j;
                }
                pos  += take;
                need -= take;
            }
        }
    }
    __syncthreads();

    // ---- Phase C: attention (head-per-warp) ------------------------------
    int idx_l = s_nbr[lane];

    // V gather: warp w loads rows w*4 .. w*4+3 (float4, coalesced)
    #pragma unroll
    for (int u = 0; u < 4; u++) {
        int jj = w*4 + u;
        int r = s_nbr[jj];
        const float4* src = (const float4*)(g_qkv + (size_t)r*384 + 256);
        ((float4*)s_v[jj])[lane] = src[lane];
    }

    // scores: head h = w, lane = neighbor
    {
        const float4* kp = (const float4*)(g_qkv + (size_t)idx_l*384 + 128 + w*DHEAD);
        const float4* qp = (const float4*)(g_qkv + (size_t)i*384 + w*DHEAD);
        float4 q0 = qp[0], q1 = qp[1], q2 = qp[2], q3 = qp[3];
        float4 k0 = kp[0], k1 = kp[1], k2 = kp[2], k3 = kp[3];
        float s = dot4(q0,k0) + dot4(q1,k1) + dot4(q2,k2) + dot4(q3,k3);
        s *= 0.25f;   // 1/sqrt(16)

        float m = s;
        #pragma unroll
        for (int off = 16; off; off >>= 1)
            m = fmaxf(m, __shfl_xor_sync(0xffffffffu, m, off));
        float p = expf(s - m);
        float den = p;
        #pragma unroll
        for (int off = 16; off; off >>= 1)
            den += __shfl_xor_sync(0xffffffffu, den, off);
        s_p[w][lane] = p / den;
    }
    __syncthreads();

    if (tid < 128) {
        int hh = tid >> 4, d = tid & 15;
        float o = 0.f;
        #pragma unroll
        for (int j = 0; j < KNBR; j++)
            o += s_p[hh][j] * s_v[j][hh*DHEAD + d];
        g_o[i*EMB + tid] = o;
    }
}

// ---------------------------------------------------------------------------
extern "C" void kernel_launch(void* const* d_in, const int* in_sizes, int n_in,
                              void* d_out, int out_size)
{
    const float* x       = (const float*)d_in[0];
    const float* coords9 = (const float*)d_in[1];
    const float* prompt  = (const float*)d_in[2];
    const float* pe_w    = (const float*)d_in[3];
    const float* pe_b    = (const float*)d_in[4];
    const float* pe_g    = (const float*)d_in[5];
    const float* pe_bt   = (const float*)d_in[6];
    const float* in_w    = (const float*)d_in[7];
    const float* in_b    = (const float*)d_in[8];
    const float* out_w   = (const float*)d_in[9];
    const float* out_b   = (const float*)d_in[10];
    float* out = (float*)d_out;

    int n = in_sizes[0] / EMB;   // 2000

    prep_kernel<<<(n + 3) / 4, 128>>>(x, coords9, prompt, pe_w, pe_b, pe_g, pe_bt, n);
    qkv_gemm_kernel<<<dim3((3*EMB)/64, (n + 15) / 16), 256>>>(in_w, in_b, n);
    fused_attn_kernel<<<n, 256>>>(n);
    out_gemm_kernel<<<dim3(EMB/64, (n + 15) / 16), 256>>>(out_w, out_b, out, n);
}

// round 5
// speedup vs baseline: 2.6111x; 1.0914x over previous
#include <cuda_runtime.h>
#include <cuda_bf16.h>
#include <math.h>

#define EMB 128
#define NHEAD 8
#define DHEAD 16
#define KNBR 32
#define NMAX 2048

// Scratch (no cudaMalloc allowed)
__device__ float4 g_cent[NMAX];
__device__ float  g_qkv [NMAX * 3 * EMB];
__device__ float  g_o   [NMAX * EMB];

__device__ __forceinline__ float dot4(float4 a, float4 b) {
    return a.x*b.x + a.y*b.y + a.z*b.z + a.w*b.w;
}

// ---------------------------------------------------------------------------
// QKV GEMM with fused input prep. Block tile: 32 rows x 64 cols, 256 threads.
// Each block computes pos_enhanced for its 32 rows directly into As:
//   pos[:96] = x + prompt, pos[96:] = LN(GELU(cent @ pe_w)).
// Col-block 0 also writes g_cent. Dynamic smem: As 16KB + Ws 33.8KB.
// ---------------------------------------------------------------------------
__global__ __launch_bounds__(256) void qkv_gemm_kernel(
    const float* __restrict__ x, const float* __restrict__ coords9,
    const float* __restrict__ prompt,
    const float* __restrict__ pe_w, const float* __restrict__ pe_b,
    const float* __restrict__ pe_g, const float* __restrict__ pe_bt,
    const float* __restrict__ W, const float* __restrict__ bias, int n)
{
    extern __shared__ float smem[];
    float* As = smem;                 // 32*128
    float* Ws = smem + 32*128;        // 64*132 (padded)

    int row0 = blockIdx.y * 32;
    int col0 = blockIdx.x * 64;
    int tid  = threadIdx.x;
    int w    = tid >> 5;
    int lane = tid & 31;

    // ---- load W tile (issue LDGs early) ----
    #pragma unroll
    for (int u = 0; u < 8; u++) {
        int lin = tid + u*256;
        int cc = lin >> 5, k4 = lin & 31;
        float4 wv = ((const float4*)(W + (size_t)(col0 + cc)*128))[k4];
        ((float4*)(Ws + cc*132))[k4] = wv;
    }

    // ---- fused prep: warp w computes rows w*4 .. w*4+3 ----
    #pragma unroll 1
    for (int u = 0; u < 4; u++) {
        int r = w*4 + u;
        int i = row0 + r;
        if (i >= n) {
            As[r*128 + lane] = 0.f; As[r*128 + 32 + lane] = 0.f;
            As[r*128 + 64 + lane] = 0.f; As[r*128 + 96 + lane] = 0.f;
            continue;
        }
        float cv = (lane < 9) ? coords9[i*9 + lane] : 0.f;
        const float inv3 = 1.0f / 3.0f;
        float cx = (__shfl_sync(0xffffffffu, cv, 0) + __shfl_sync(0xffffffffu, cv, 3) + __shfl_sync(0xffffffffu, cv, 6)) * inv3;
        float cy = (__shfl_sync(0xffffffffu, cv, 1) + __shfl_sync(0xffffffffu, cv, 4) + __shfl_sync(0xffffffffu, cv, 7)) * inv3;
        float cz = (__shfl_sync(0xffffffffu, cv, 2) + __shfl_sync(0xffffffffu, cv, 5) + __shfl_sync(0xffffffffu, cv, 8)) * inv3;
        if (col0 == 0 && lane == 0) g_cent[i] = make_float4(cx, cy, cz, 0.f);

        float v = cx*pe_w[lane] + cy*pe_w[32+lane] + cz*pe_w[64+lane] + pe_b[lane];
        float h = 0.5f * v * (1.0f + erff(v * 0.70710678118654752f));

        float s = h, s2 = h*h;
        #pragma unroll
        for (int off = 16; off; off >>= 1) {
            s  += __shfl_xor_sync(0xffffffffu, s,  off);
            s2 += __shfl_xor_sync(0xffffffffu, s2, off);
        }
        float mu  = s * (1.0f/32.0f);
        float var = s2 * (1.0f/32.0f) - mu*mu;
        float inv = rsqrtf(var + 1e-5f);

        As[r*128 +      lane] = x[i*EMB +      lane] + prompt[     lane];
        As[r*128 + 32 + lane] = x[i*EMB + 32 + lane] + prompt[32 + lane];
        As[r*128 + 64 + lane] = x[i*EMB + 64 + lane] + prompt[64 + lane];
        As[r*128 + 96 + lane] = (h - mu) * inv * pe_g[lane] + pe_bt[lane];
    }
    __syncthreads();

    // ---- compute: thread -> 4 rows x 2 cols ----
    int tx = tid & 31;
    int ty = tid >> 5;
    const float4* w0p = (const float4*)(Ws + tx*132);
    const float4* w1p = (const float4*)(Ws + (tx+32)*132);

    float acc[4][2] = {{0.f,0.f},{0.f,0.f},{0.f,0.f},{0.f,0.f}};
    #pragma unroll
    for (int k4 = 0; k4 < 32; k4++) {
        float4 w0 = w0p[k4], w1 = w1p[k4];
        #pragma unroll
        for (int r = 0; r < 4; r++) {
            float4 a = ((const float4*)(As + (ty*4+r)*128))[k4];
            acc[r][0] += dot4(a, w0);
            acc[r][1] += dot4(a, w1);
        }
    }

    int c0 = col0 + tx, c1 = col0 + tx + 32;
    float b0 = bias[c0], b1 = bias[c1];
    #pragma unroll
    for (int r = 0; r < 4; r++) {
        int gr = row0 + ty*4 + r;
        if (gr < n) {
            g_qkv[(size_t)gr*384 + c0] = acc[r][0] + b0;
            g_qkv[(size_t)gr*384 + c1] = acc[r][1] + b1;
        }
    }
}

// ---------------------------------------------------------------------------
// Output GEMM: 32 rows x 64 cols tiles over g_o @ out_w.T, with sanitize.
// ---------------------------------------------------------------------------
__global__ __launch_bounds__(256) void out_gemm_kernel(
    const float* __restrict__ W, const float* __restrict__ bias,
    float* __restrict__ C, int n)
{
    extern __shared__ float smem[];
    float* As = smem;                 // 32*128
    float* Ws = smem + 32*128;        // 64*132

    int row0 = blockIdx.y * 32;
    int col0 = blockIdx.x * 64;
    int tid  = threadIdx.x;

    #pragma unroll
    for (int u = 0; u < 8; u++) {
        int lin = tid + u*256;
        int cc = lin >> 5, k4 = lin & 31;
        float4 wv = ((const float4*)(W + (size_t)(col0 + cc)*128))[k4];
        ((float4*)(Ws + cc*132))[k4] = wv;
    }
    #pragma unroll
    for (int u = 0; u < 4; u++) {
        int lin = tid + u*256;
        int r = lin >> 5, c4 = lin & 31;
        int gr = row0 + r;
        float4 av = make_float4(0.f,0.f,0.f,0.f);
        if (gr < n) av = ((const float4*)(g_o + (size_t)gr*128))[c4];
        ((float4*)(As + r*128))[c4] = av;
    }
    __syncthreads();

    int tx = tid & 31;
    int ty = tid >> 5;
    const float4* w0p = (const float4*)(Ws + tx*132);
    const float4* w1p = (const float4*)(Ws + (tx+32)*132);

    float acc[4][2] = {{0.f,0.f},{0.f,0.f},{0.f,0.f},{0.f,0.f}};
    #pragma unroll
    for (int k4 = 0; k4 < 32; k4++) {
        float4 w0 = w0p[k4], w1 = w1p[k4];
        #pragma unroll
        for (int r = 0; r < 4; r++) {
            float4 a = ((const float4*)(As + (ty*4+r)*128))[k4];
            acc[r][0] += dot4(a, w0);
            acc[r][1] += dot4(a, w1);
        }
    }

    int c0 = col0 + tx, c1 = col0 + tx + 32;
    float b0 = bias[c0], b1 = bias[c1];
    #pragma unroll
    for (int r = 0; r < 4; r++) {
        int gr = row0 + ty*4 + r;
        if (gr < n) {
            float v0 = acc[r][0] + b0;
            float v1 = acc[r][1] + b1;
            if (isnan(v0)) v0 = 0.f;
            if (isnan(v1)) v1 = 0.f;
            v0 = fminf(fmaxf(v0, -1e4f), 1e4f);
            v1 = fminf(fmaxf(v1, -1e4f), 1e4f);
            C[(size_t)gr*EMB + c0] = v0;
            C[(size_t)gr*EMB + c1] = v1;
        }
    }
}

// ---------------------------------------------------------------------------
// Fused top-K + sparse attention. One block (256 threads) per node.
// Radix select (exact, 4x8-bit levels) -> neighbor set -> head-per-warp
// attention with register-prefetched V and deterministic partial-sum reduce.
// ---------------------------------------------------------------------------
__global__ __launch_bounds__(256) void fused_attn_kernel(int n)
{
    __shared__ unsigned s_key[NMAX];          // 8 KB
    __shared__ unsigned s_hist[256];          // 1 KB
    __shared__ float    s_p[NHEAD][KNBR];     // 1 KB
    __shared__ float    s_part[NHEAD][EMB];   // 4 KB
    __shared__ int      s_nbr[KNBR];
    __shared__ unsigned s_Tkey, s_rem;
    __shared__ int      s_cnt;

    int i    = blockIdx.x;
    int tid  = threadIdx.x;
    int w    = tid >> 5;
    int lane = tid & 31;

    // ---- Phase A: keys + level-0 histogram -------------------------------
    s_hist[tid] = 0u;
    if (tid == 0) { s_Tkey = 0u; s_rem = KNBR; s_cnt = 0; }
    __syncthreads();

    float4 c0 = g_cent[i];
    #pragma unroll
    for (int u = 0; u < NMAX/256; u++) {
        int j = tid + u*256;
        unsigned k = 0xFFFFFFFFu;   // pad bin 255, unreachable by finite keys
        if (j < n) {
            float4 cj = g_cent[j];
            float dx = cj.x - c0.x, dy = cj.y - c0.y, dz = cj.z - c0.z;
            k = __float_as_uint(dx*dx + dy*dy + dz*dz);
        }
        s_key[j] = k;
        atomicAdd(&s_hist[k >> 24], 1u);
    }
    __syncthreads();

    // ---- radix descent ---------------------------------------------------
    #pragma unroll 1
    for (int level = 0; level < 4; level++) {
        int shift = 24 - level*8;

        if (tid < 32) {
            unsigned h[8]; unsigned lsum = 0u;
            #pragma unroll
            for (int u = 0; u < 8; u++) { h[u] = s_hist[lane*8 + u]; lsum += h[u]; }
            unsigned incl = lsum;
            #pragma unroll
            for (int off = 1; off < 32; off <<= 1) {
                unsigned v = __shfl_up_sync(0xffffffffu, incl, off);
                if (lane >= off) incl += v;
            }
            unsigned cum = incl - lsum;
            unsigned rem = s_rem;
            int bloc = -1; unsigned cb_loc = 0u;
            #pragma unroll
            for (int u = 0; u < 8; u++) {
                if (cum < rem && cum + h[u] >= rem) { bloc = lane*8 + u; cb_loc = cum; }
                cum += h[u];
            }
            unsigned bal = __ballot_sync(0xffffffffu, bloc >= 0);
            int src = __ffs(bal) - 1;
            if (lane == src) {
                s_Tkey |= ((unsigned)bloc) << shift;
                s_rem   = rem - cb_loc;
            }
        }
        __syncthreads();

        if (level < 3) {
            unsigned pref = s_Tkey >> shift;
            s_hist[tid] = 0u;
            __syncthreads();
            #pragma unroll
            for (int u = 0; u < NMAX/256; u++) {
                unsigned k = s_key[tid + u*256];
                if ((k >> shift) == pref)
                    atomicAdd(&s_hist[(k >> (shift - 8)) & 0xFFu], 1u);
            }
            __syncthreads();
        }
    }

    // ---- Phase B: emission (set semantics; ties at T ascending index) ----
    unsigned T = s_Tkey;
    #pragma unroll
    for (int u = 0; u < NMAX/256; u++) {
        int j = tid + u*256;
        if (s_key[j] < T) {
            int p = atomicAdd(&s_cnt, 1);
            s_nbr[p] = j;
        }
    }
    __syncthreads();

    if (tid < 32) {
        int c = s_cnt;
        int need = KNBR - c;
        int pos = c;
        #pragma unroll 1
        for (int u = 0; u < NMAX/32 && need > 0; u++) {
            int j = u*32 + lane;
            unsigned k = s_key[j];
            unsigned beq = __ballot_sync(0xffffffffu, k == T);
            if (beq) {
                int neq  = __popc(beq);
                int take = need < neq ? need : neq;
                if (k == T) {
                    int rank = __popc(beq & ((1u << lane) - 1u));
                    if (rank < take) s_nbr[pos + rank] = j;
                }
                pos  += take;
                need -= take;
            }
        }
    }
    __syncthreads();

    // ---- Phase C: attention ----------------------------------------------
    int idx_l = s_nbr[lane];
    int vrow[4];
    #pragma unroll
    for (int u = 0; u < 4; u++) vrow[u] = s_nbr[w*4 + u];

    // prefetch V rows (warp w owns neighbors 4w..4w+3); in flight under softmax
    float4 vreg[4];
    #pragma unroll
    for (int u = 0; u < 4; u++)
        vreg[u] = ((const float4*)(g_qkv + (size_t)vrow[u]*384 + 256))[lane];

    // scores: head h = w, lane = neighbor
    {
        const float4* kp = (const float4*)(g_qkv + (size_t)idx_l*384 + 128 + w*DHEAD);
        const float4* qp = (const float4*)(g_qkv + (size_t)i*384 + w*DHEAD);
        float4 q0 = qp[0], q1 = qp[1], q2 = qp[2], q3 = qp[3];
        float4 k0 = kp[0], k1 = kp[1], k2 = kp[2], k3 = kp[3];
        float s = dot4(q0,k0) + dot4(q1,k1) + dot4(q2,k2) + dot4(q3,k3);
        s *= 0.25f;   // 1/sqrt(16)

        float m = s;
        #pragma unroll
        for (int off = 16; off; off >>= 1)
            m = fmaxf(m, __shfl_xor_sync(0xffffffffu, m, off));
        float p = expf(s - m);
        float den = p;
        #pragma unroll
        for (int off = 16; off; off >>= 1)
            den += __shfl_xor_sync(0xffffffffu, den, off);
        s_p[w][lane] = p / den;
    }
    __syncthreads();

    // partial outputs: lane handles dims 4*lane..4*lane+3 (head = lane>>2)
    {
        int hh = lane >> 2;
        float4 acc = make_float4(0.f,0.f,0.f,0.f);
        #pragma unroll
        for (int u = 0; u < 4; u++) {
            float p = s_p[hh][w*4 + u];
            acc.x += p * vreg[u].x;
            acc.y += p * vreg[u].y;
            acc.z += p * vreg[u].z;
            acc.w += p * vreg[u].w;
        }
        ((float4*)s_part[w])[lane] = acc;
    }
    __syncthreads();

    // fixed-order 8-way reduce (deterministic), write g_o
    if (tid < 128) {
        float o = 0.f;
        #pragma unroll
        for (int ww = 0; ww < NHEAD; ww++) o += s_part[ww][tid];
        g_o[(size_t)i*EMB + tid] = o;
    }
}

// ---------------------------------------------------------------------------
extern "C" void kernel_launch(void* const* d_in, const int* in_sizes, int n_in,
                              void* d_out, int out_size)
{
    const float* x       = (const float*)d_in[0];
    const float* coords9 = (const float*)d_in[1];
    const float* prompt  = (const float*)d_in[2];
    const float* pe_w    = (const float*)d_in[3];
    const float* pe_b    = (const float*)d_in[4];
    const float* pe_g    = (const float*)d_in[5];
    const float* pe_bt   = (const float*)d_in[6];
    const float* in_w    = (const float*)d_in[7];
    const float* in_b    = (const float*)d_in[8];
    const float* out_w   = (const float*)d_in[9];
    const float* out_b   = (const float*)d_in[10];
    float* out = (float*)d_out;

    int n = in_sizes[0] / EMB;   // 2000
    int nrb = (n + 31) / 32;     // 63 row blocks

    const int GEMM_SMEM = (32*128 + 64*132) * (int)sizeof(float);   // 50176 B
    static int attr_done = 0;
    if (!attr_done) {
        cudaFuncSetAttribute(qkv_gemm_kernel, cudaFuncAttributeMaxDynamicSharedMemorySize, GEMM_SMEM);
        cudaFuncSetAttribute(out_gemm_kernel, cudaFuncAttributeMaxDynamicSharedMemorySize, GEMM_SMEM);
        attr_done = 1;
    }

    qkv_gemm_kernel<<<dim3(6, nrb), 256, GEMM_SMEM>>>(
        x, coords9, prompt, pe_w, pe_b, pe_g, pe_bt, in_w, in_b, n);
    fused_attn_kernel<<<n, 256>>>(n);
    out_gemm_kernel<<<dim3(2, nrb), 256, GEMM_SMEM>>>(out_w, out_b, out, n);
}

// round 6
// speedup vs baseline: 2.6834x; 1.0277x over previous
#include <cuda_runtime.h>
#include <cuda_bf16.h>
#include <math.h>

#define EMB 128
#define NHEAD 8
#define DHEAD 16
#define KNBR 32
#define NMAX 2048

// Scratch (no cudaMalloc allowed)
__device__ float4 g_cent[NMAX];
__device__ float  g_qkv [NMAX * 3 * EMB];
__device__ float  g_o   [NMAX * EMB];

__device__ __forceinline__ float dot4(float4 a, float4 b) {
    return a.x*b.x + a.y*b.y + a.z*b.z + a.w*b.w;
}

// ---------------------------------------------------------------------------
// QKV GEMM with fused input prep. Block tile: 32 rows x 128 cols, 256 threads,
// 4x4 register tile per thread. Col-block 0/1/2 = Q/K/V. Each block computes
// pos_enhanced for its 32 rows directly into As. Smem: As 16KB + Ws 67.6KB.
// ---------------------------------------------------------------------------
__global__ __launch_bounds__(256) void qkv_gemm_kernel(
    const float* __restrict__ x, const float* __restrict__ coords9,
    const float* __restrict__ prompt,
    const float* __restrict__ pe_w, const float* __restrict__ pe_b,
    const float* __restrict__ pe_g, const float* __restrict__ pe_bt,
    const float* __restrict__ W, const float* __restrict__ bias, int n)
{
    extern __shared__ float smem[];
    float* As = smem;                 // 32*128
    float* Ws = smem + 32*128;        // 128*132 (padded)

    int row0 = blockIdx.y * 32;
    int col0 = blockIdx.x * 128;
    int tid  = threadIdx.x;
    int w    = tid >> 5;
    int lane = tid & 31;

    // ---- load W tile: 128 cols x 128 k ----
    #pragma unroll
    for (int u = 0; u < 16; u++) {
        int lin = tid + u*256;
        int cc = lin >> 5, k4 = lin & 31;
        float4 wv = ((const float4*)(W + (size_t)(col0 + cc)*128))[k4];
        ((float4*)(Ws + cc*132))[k4] = wv;
    }

    // ---- fused prep: warp w computes rows w*4 .. w*4+3 ----
    #pragma unroll 1
    for (int u = 0; u < 4; u++) {
        int r = w*4 + u;
        int i = row0 + r;
        if (i >= n) {
            As[r*128 + lane] = 0.f; As[r*128 + 32 + lane] = 0.f;
            As[r*128 + 64 + lane] = 0.f; As[r*128 + 96 + lane] = 0.f;
            continue;
        }
        float cv = (lane < 9) ? coords9[i*9 + lane] : 0.f;
        const float inv3 = 1.0f / 3.0f;
        float cx = (__shfl_sync(0xffffffffu, cv, 0) + __shfl_sync(0xffffffffu, cv, 3) + __shfl_sync(0xffffffffu, cv, 6)) * inv3;
        float cy = (__shfl_sync(0xffffffffu, cv, 1) + __shfl_sync(0xffffffffu, cv, 4) + __shfl_sync(0xffffffffu, cv, 7)) * inv3;
        float cz = (__shfl_sync(0xffffffffu, cv, 2) + __shfl_sync(0xffffffffu, cv, 5) + __shfl_sync(0xffffffffu, cv, 8)) * inv3;
        if (col0 == 0 && lane == 0) g_cent[i] = make_float4(cx, cy, cz, 0.f);

        float v = cx*pe_w[lane] + cy*pe_w[32+lane] + cz*pe_w[64+lane] + pe_b[lane];
        float h = 0.5f * v * (1.0f + erff(v * 0.70710678118654752f));

        float s = h, s2 = h*h;
        #pragma unroll
        for (int off = 16; off; off >>= 1) {
            s  += __shfl_xor_sync(0xffffffffu, s,  off);
            s2 += __shfl_xor_sync(0xffffffffu, s2, off);
        }
        float mu  = s * (1.0f/32.0f);
        float var = s2 * (1.0f/32.0f) - mu*mu;
        float inv = rsqrtf(var + 1e-5f);

        As[r*128 +      lane] = x[i*EMB +      lane] + prompt[     lane];
        As[r*128 + 32 + lane] = x[i*EMB + 32 + lane] + prompt[32 + lane];
        As[r*128 + 64 + lane] = x[i*EMB + 64 + lane] + prompt[64 + lane];
        As[r*128 + 96 + lane] = (h - mu) * inv * pe_g[lane] + pe_bt[lane];
    }
    __syncthreads();

    // ---- compute: thread -> 4 rows x 4 cols ----
    int tx = tid & 31;
    int ty = tid >> 5;
    const float4* wp0 = (const float4*)(Ws + (tx      )*132);
    const float4* wp1 = (const float4*)(Ws + (tx + 32 )*132);
    const float4* wp2 = (const float4*)(Ws + (tx + 64 )*132);
    const float4* wp3 = (const float4*)(Ws + (tx + 96 )*132);
    const float4* ap0 = (const float4*)(As + (ty*4 + 0)*128);
    const float4* ap1 = (const float4*)(As + (ty*4 + 1)*128);
    const float4* ap2 = (const float4*)(As + (ty*4 + 2)*128);
    const float4* ap3 = (const float4*)(As + (ty*4 + 3)*128);

    float acc[4][4];
    #pragma unroll
    for (int r = 0; r < 4; r++)
        #pragma unroll
        for (int c = 0; c < 4; c++) acc[r][c] = 0.f;

    #pragma unroll
    for (int k4 = 0; k4 < 32; k4++) {
        float4 w0 = wp0[k4], w1 = wp1[k4], w2 = wp2[k4], w3 = wp3[k4];
        float4 a0 = ap0[k4], a1 = ap1[k4], a2 = ap2[k4], a3 = ap3[k4];
        acc[0][0] += dot4(a0,w0); acc[0][1] += dot4(a0,w1); acc[0][2] += dot4(a0,w2); acc[0][3] += dot4(a0,w3);
        acc[1][0] += dot4(a1,w0); acc[1][1] += dot4(a1,w1); acc[1][2] += dot4(a1,w2); acc[1][3] += dot4(a1,w3);
        acc[2][0] += dot4(a2,w0); acc[2][1] += dot4(a2,w1); acc[2][2] += dot4(a2,w2); acc[2][3] += dot4(a2,w3);
        acc[3][0] += dot4(a3,w0); acc[3][1] += dot4(a3,w1); acc[3][2] += dot4(a3,w2); acc[3][3] += dot4(a3,w3);
    }

    float bv[4];
    #pragma unroll
    for (int c = 0; c < 4; c++) bv[c] = bias[col0 + tx + 32*c];
    #pragma unroll
    for (int r = 0; r < 4; r++) {
        int gr = row0 + ty*4 + r;
        if (gr < n) {
            #pragma unroll
            for (int c = 0; c < 4; c++)
                g_qkv[(size_t)gr*384 + col0 + tx + 32*c] = acc[r][c] + bv[c];
        }
    }
}

// ---------------------------------------------------------------------------
// Output GEMM: 32 rows x 64 cols tiles over g_o @ out_w.T, with sanitize.
// ---------------------------------------------------------------------------
__global__ __launch_bounds__(256) void out_gemm_kernel(
    const float* __restrict__ W, const float* __restrict__ bias,
    float* __restrict__ C, int n)
{
    extern __shared__ float smem[];
    float* As = smem;                 // 32*128
    float* Ws = smem + 32*128;        // 64*132

    int row0 = blockIdx.y * 32;
    int col0 = blockIdx.x * 64;
    int tid  = threadIdx.x;

    #pragma unroll
    for (int u = 0; u < 8; u++) {
        int lin = tid + u*256;
        int cc = lin >> 5, k4 = lin & 31;
        float4 wv = ((const float4*)(W + (size_t)(col0 + cc)*128))[k4];
        ((float4*)(Ws + cc*132))[k4] = wv;
    }
    #pragma unroll
    for (int u = 0; u < 4; u++) {
        int lin = tid + u*256;
        int r = lin >> 5, c4 = lin & 31;
        int gr = row0 + r;
        float4 av = make_float4(0.f,0.f,0.f,0.f);
        if (gr < n) av = ((const float4*)(g_o + (size_t)gr*128))[c4];
        ((float4*)(As + r*128))[c4] = av;
    }
    __syncthreads();

    int tx = tid & 31;
    int ty = tid >> 5;
    const float4* w0p = (const float4*)(Ws + tx*132);
    const float4* w1p = (const float4*)(Ws + (tx+32)*132);

    float acc[4][2] = {{0.f,0.f},{0.f,0.f},{0.f,0.f},{0.f,0.f}};
    #pragma unroll
    for (int k4 = 0; k4 < 32; k4++) {
        float4 w0 = w0p[k4], w1 = w1p[k4];
        #pragma unroll
        for (int r = 0; r < 4; r++) {
            float4 a = ((const float4*)(As + (ty*4+r)*128))[k4];
            acc[r][0] += dot4(a, w0);
            acc[r][1] += dot4(a, w1);
        }
    }

    int c0 = col0 + tx, c1 = col0 + tx + 32;
    float b0 = bias[c0], b1 = bias[c1];
    #pragma unroll
    for (int r = 0; r < 4; r++) {
        int gr = row0 + ty*4 + r;
        if (gr < n) {
            float v0 = acc[r][0] + b0;
            float v1 = acc[r][1] + b1;
            if (isnan(v0)) v0 = 0.f;
            if (isnan(v1)) v1 = 0.f;
            v0 = fminf(fmaxf(v0, -1e4f), 1e4f);
            v1 = fminf(fmaxf(v1, -1e4f), 1e4f);
            C[(size_t)gr*EMB + c0] = v0;
            C[(size_t)gr*EMB + c1] = v1;
        }
    }
}

// ---------------------------------------------------------------------------
// Fused top-K + sparse attention. One block (256 threads) per node.
// Radix select (exact, 4x8-bit levels) with register-resident keys for the
// rescan/emission passes, then head-per-warp attention.
// ---------------------------------------------------------------------------
__global__ __launch_bounds__(256) void fused_attn_kernel(int n)
{
    __shared__ unsigned s_key[NMAX];          // 8 KB (warp-0 tie pass)
    __shared__ unsigned s_hist[256];          // 1 KB
    __shared__ float    s_p[NHEAD][KNBR];     // 1 KB
    __shared__ float    s_part[NHEAD][EMB];   // 4 KB
    __shared__ int      s_nbr[KNBR];
    __shared__ unsigned s_Tkey, s_rem;
    __shared__ int      s_cnt;

    int i    = blockIdx.x;
    int tid  = threadIdx.x;
    int w    = tid >> 5;
    int lane = tid & 31;

    // ---- Phase A: keys (kept in registers) + level-0 histogram -----------
    s_hist[tid] = 0u;
    if (tid == 0) { s_Tkey = 0u; s_rem = KNBR; s_cnt = 0; }
    __syncthreads();

    float4 c0 = g_cent[i];
    unsigned kreg[NMAX/256];
    #pragma unroll
    for (int u = 0; u < NMAX/256; u++) {
        int j = tid + u*256;
        unsigned k = 0xFFFFFFFFu;   // pad bin 255, unreachable by finite keys
        if (j < n) {
            float4 cj = g_cent[j];
            float dx = cj.x - c0.x, dy = cj.y - c0.y, dz = cj.z - c0.z;
            k = __float_as_uint(dx*dx + dy*dy + dz*dz);
        }
        kreg[u] = k;
        s_key[j] = k;
        atomicAdd(&s_hist[k >> 24], 1u);
    }
    __syncthreads();

    // ---- radix descent ---------------------------------------------------
    #pragma unroll 1
    for (int level = 0; level < 4; level++) {
        int shift = 24 - level*8;

        if (tid < 32) {
            unsigned h[8]; unsigned lsum = 0u;
            #pragma unroll
            for (int u = 0; u < 8; u++) { h[u] = s_hist[lane*8 + u]; lsum += h[u]; }
            unsigned incl = lsum;
            #pragma unroll
            for (int off = 1; off < 32; off <<= 1) {
                unsigned v = __shfl_up_sync(0xffffffffu, incl, off);
                if (lane >= off) incl += v;
            }
            unsigned cum = incl - lsum;
            unsigned rem = s_rem;
            int bloc = -1; unsigned cb_loc = 0u;
            #pragma unroll
            for (int u = 0; u < 8; u++) {
                if (cum < rem && cum + h[u] >= rem) { bloc = lane*8 + u; cb_loc = cum; }
                cum += h[u];
            }
            unsigned bal = __ballot_sync(0xffffffffu, bloc >= 0);
            int src = __ffs(bal) - 1;
            if (lane == src) {
                s_Tkey |= ((unsigned)bloc) << shift;
                s_rem   = rem - cb_loc;
            }
        }
        __syncthreads();

        if (level < 3) {
            unsigned pref = s_Tkey >> shift;
            s_hist[tid] = 0u;
            __syncthreads();
            #pragma unroll
            for (int u = 0; u < NMAX/256; u++) {
                unsigned k = kreg[u];
                if ((k >> shift) == pref)
                    atomicAdd(&s_hist[(k >> (shift - 8)) & 0xFFu], 1u);
            }
            __syncthreads();
        }
    }

    // ---- Phase B: emission (set semantics; ties at T ascending index) ----
    unsigned T = s_Tkey;
    #pragma unroll
    for (int u = 0; u < NMAX/256; u++) {
        if (kreg[u] < T) {
            int p = atomicAdd(&s_cnt, 1);
            s_nbr[p] = tid + u*256;
        }
    }
    __syncthreads();

    if (tid < 32) {
        int c = s_cnt;
        int need = KNBR - c;
        int pos = c;
        #pragma unroll 1
        for (int u = 0; u < NMAX/32 && need > 0; u++) {
            int j = u*32 + lane;
            unsigned k = s_key[j];
            unsigned beq = __ballot_sync(0xffffffffu, k == T);
            if (beq) {
                int neq  = __popc(beq);
                int take = need < neq ? need : neq;
                if (k == T) {
                    int rank = __popc(beq & ((1u << lane) - 1u));
                    if (rank < take) s_nbr[pos + rank] = j;
                }
                pos  += take;
                need -= take;
            }
        }
    }
    __syncthreads();

    // ---- Phase C: attention ----------------------------------------------
    int idx_l = s_nbr[lane];
    int vrow[4];
    #pragma unroll
    for (int u = 0; u < 4; u++) vrow[u] = s_nbr[w*4 + u];

    float4 vreg[4];
    #pragma unroll
    for (int u = 0; u < 4; u++)
        vreg[u] = ((const float4*)(g_qkv + (size_t)vrow[u]*384 + 256))[lane];

    {
        const float4* kp = (const float4*)(g_qkv + (size_t)idx_l*384 + 128 + w*DHEAD);
        const float4* qp = (const float4*)(g_qkv + (size_t)i*384 + w*DHEAD);
        float4 q0 = qp[0], q1 = qp[1], q2 = qp[2], q3 = qp[3];
        float4 k0 = kp[0], k1 = kp[1], k2 = kp[2], k3 = kp[3];
        float s = dot4(q0,k0) + dot4(q1,k1) + dot4(q2,k2) + dot4(q3,k3);
        s *= 0.25f;   // 1/sqrt(16)

        float m = s;
        #pragma unroll
        for (int off = 16; off; off >>= 1)
            m = fmaxf(m, __shfl_xor_sync(0xffffffffu, m, off));
        float p = expf(s - m);
        float den = p;
        #pragma unroll
        for (int off = 16; off; off >>= 1)
            den += __shfl_xor_sync(0xffffffffu, den, off);
        s_p[w][lane] = p / den;
    }
    __syncthreads();

    {
        int hh = lane >> 2;
        float4 acc = make_float4(0.f,0.f,0.f,0.f);
        #pragma unroll
        for (int u = 0; u < 4; u++) {
            float p = s_p[hh][w*4 + u];
            acc.x += p * vreg[u].x;
            acc.y += p * vreg[u].y;
            acc.z += p * vreg[u].z;
            acc.w += p * vreg[u].w;
        }
        ((float4*)s_part[w])[lane] = acc;
    }
    __syncthreads();

    if (tid < 128) {
        float o = 0.f;
        #pragma unroll
        for (int ww = 0; ww < NHEAD; ww++) o += s_part[ww][tid];
        g_o[(size_t)i*EMB + tid] = o;
    }
}

// ---------------------------------------------------------------------------
extern "C" void kernel_launch(void* const* d_in, const int* in_sizes, int n_in,
                              void* d_out, int out_size)
{
    const float* x       = (const float*)d_in[0];
    const float* coords9 = (const float*)d_in[1];
    const float* prompt  = (const float*)d_in[2];
    const float* pe_w    = (const float*)d_in[3];
    const float* pe_b    = (const float*)d_in[4];
    const float* pe_g    = (const float*)d_in[5];
    const float* pe_bt   = (const float*)d_in[6];
    const float* in_w    = (const float*)d_in[7];
    const float* in_b    = (const float*)d_in[8];
    const float* out_w   = (const float*)d_in[9];
    const float* out_b   = (const float*)d_in[10];
    float* out = (float*)d_out;

    int n = in_sizes[0] / EMB;   // 2000
    int nrb = (n + 31) / 32;     // 63 row blocks

    const int QKV_SMEM = (32*128 + 128*132) * (int)sizeof(float);   // 83968 B
    const int OUT_SMEM = (32*128 +  64*132) * (int)sizeof(float);   // 50176 B
    cudaFuncSetAttribute(qkv_gemm_kernel, cudaFuncAttributeMaxDynamicSharedMemorySize, QKV_SMEM);
    cudaFuncSetAttribute(out_gemm_kernel, cudaFuncAttributeMaxDynamicSharedMemorySize, OUT_SMEM);

    qkv_gemm_kernel<<<dim3(3, nrb), 256, QKV_SMEM>>>(
        x, coords9, prompt, pe_w, pe_b, pe_g, pe_bt, in_w, in_b, n);
    fused_attn_kernel<<<n, 256>>>(n);
    out_gemm_kernel<<<dim3(2, nrb), 256, OUT_SMEM>>>(out_w, out_b, out, n);
}